// round 4
// baseline (speedup 1.0000x reference)
#include <cuda_runtime.h>
#include <math.h>

#define N_TOK 2304

// Scratch (device globals: allocation-free per harness rules)
__device__ float g_qkv[2u * 1536u * 2304u];   // (B, 3*512, N)
__device__ float g_inv[2 * 1024];             // inv L2 norms: q rows 0..511, k rows 512..1023
__device__ float g_att[2u * 512u * 2304u];    // attention output (B, 512, N)
__device__ float g_w1[1536 * 256];            // tf32-rounded w_qkv
__device__ float g_w2[256 * 512];             // tf32-rounded w_proj

__device__ __forceinline__ float to_tf32(float x) {
    float r;
    asm("cvt.rna.tf32.f32 %0, %1;" : "=f"(r) : "f"(x));
    return r;
}
__device__ __forceinline__ unsigned fb(float x) { return __float_as_uint(x); }

__device__ __forceinline__ void mma_tf32(float* d, const unsigned* a, const unsigned* b) {
    asm volatile(
        "mma.sync.aligned.m16n8k8.row.col.f32.tf32.tf32.f32 "
        "{%0,%1,%2,%3}, {%4,%5,%6,%7}, {%8,%9}, {%0,%1,%2,%3};\n"
        : "+f"(d[0]), "+f"(d[1]), "+f"(d[2]), "+f"(d[3])
        : "r"(a[0]), "r"(a[1]), "r"(a[2]), "r"(a[3]), "r"(b[0]), "r"(b[1]));
}

__device__ __forceinline__ void cp16(unsigned dst, const void* src) {
    asm volatile("cp.async.ca.shared.global [%0], [%1], 16;" :: "r"(dst), "l"(src));
}
#define CP_COMMIT asm volatile("cp.async.commit_group;")
#define CP_WAIT(n) asm volatile("cp.async.wait_group %0;" :: "n"(n))

// ---------------------------------------------------------------------------
// Pre-round weights to tf32 (once, cheap)
// ---------------------------------------------------------------------------
__global__ void round_w(const float* __restrict__ a, const float* __restrict__ b,
                        float* __restrict__ wa, float* __restrict__ wb,
                        int na, int nb) {
    int i = blockIdx.x * 256 + threadIdx.x;
    if (i < na) wa[i] = to_tf32(a[i]);
    if (i < nb) wb[i] = to_tf32(b[i]);
}

// ---------------------------------------------------------------------------
// tf32 GEMM: Y[b][m][n] = sum_k W[m][k]*X[b][k][n] (+bias[m])
// Block tile BM x 128, 8 warps (4m x 2n), warp WM x 64, k-chunk 16, cp.async x2.
// ---------------------------------------------------------------------------
template <int BM, int WM>
__global__ __launch_bounds__(256) void gemm2(
    const float* __restrict__ W, const float* __restrict__ X,
    const float* __restrict__ bias, float* __restrict__ Y, int K, int Mtot) {
    constexpr int NG = WM / 16;
    __shared__ float As[2][BM * 20];     // [m][k] stride 20
    __shared__ float Bs[2][16 * 136];    // [k][n] stride 136

    const int tid = threadIdx.x, lane = tid & 31, w = tid >> 5;
    const int g = lane >> 2, tg = lane & 3;
    const int wm0 = (w & 3) * WM, wn0 = (w >> 2) * 64;
    const int n0 = blockIdx.x * 128;
    const int m0 = blockIdx.y * BM;
    const int b  = blockIdx.z;
    const float* Xb = X + (size_t)b * K * N_TOK;
    float* Yb = Y + (size_t)b * Mtot * N_TOK;

    const unsigned sA = (unsigned)__cvta_generic_to_shared(&As[0][0]);
    const unsigned sB = (unsigned)__cvta_generic_to_shared(&Bs[0][0]);

    float acc[NG][8][4] = {};

    auto issue = [&](int k0, int buf) {
#pragma unroll
        for (int e = tid; e < BM * 4; e += 256) {
            int m = e >> 2, kq = e & 3;
            cp16(sA + (buf * BM * 20 + m * 20 + kq * 4) * 4,
                 W + (size_t)(m0 + m) * K + k0 + kq * 4);
        }
#pragma unroll
        for (int e = tid; e < 512; e += 256) {
            int kk = e >> 5, nq = e & 31;
            cp16(sB + (buf * 16 * 136 + kk * 136 + nq * 4) * 4,
                 Xb + (size_t)(k0 + kk) * N_TOK + n0 + nq * 4);
        }
        CP_COMMIT;
    };

    issue(0, 0);
    for (int k0 = 0; k0 < K; k0 += 16) {
        int buf = (k0 >> 4) & 1;
        if (k0 + 16 < K) { issue(k0 + 16, buf ^ 1); CP_WAIT(1); }
        else             { CP_WAIT(0); }
        __syncthreads();
        const float* Ab = As[buf];
        const float* Bb = Bs[buf];
#pragma unroll
        for (int kc = 0; kc < 16; kc += 8) {
            unsigned a[NG][4];
#pragma unroll
            for (int s = 0; s < NG; s++) {
                int r = wm0 + 16 * s + g;
                a[s][0] = fb(Ab[r * 20 + kc + tg]);
                a[s][1] = fb(Ab[(r + 8) * 20 + kc + tg]);
                a[s][2] = fb(Ab[r * 20 + kc + tg + 4]);
                a[s][3] = fb(Ab[(r + 8) * 20 + kc + tg + 4]);
            }
#pragma unroll
            for (int nf = 0; nf < 8; nf++) {
                unsigned bb[2];
                bb[0] = fb(Bb[(kc + tg) * 136 + wn0 + nf * 8 + g]);
                bb[1] = fb(Bb[(kc + tg + 4) * 136 + wn0 + nf * 8 + g]);
#pragma unroll
                for (int s = 0; s < NG; s++) mma_tf32(acc[s][nf], a[s], bb);
            }
        }
        __syncthreads();
    }
#pragma unroll
    for (int s = 0; s < NG; s++) {
        int r0 = m0 + wm0 + 16 * s + g, r1 = r0 + 8;
        float bv0 = bias ? bias[r0] : 0.f;
        float bv1 = bias ? bias[r1] : 0.f;
#pragma unroll
        for (int nf = 0; nf < 8; nf++) {
            *(float2*)(Yb + (size_t)r0 * N_TOK + n0 + wn0 + nf * 8 + tg * 2) =
                make_float2(acc[s][nf][0] + bv0, acc[s][nf][1] + bv0);
            *(float2*)(Yb + (size_t)r1 * N_TOK + n0 + wn0 + nf * 8 + tg * 2) =
                make_float2(acc[s][nf][2] + bv1, acc[s][nf][3] + bv1);
        }
    }
}

// ---------------------------------------------------------------------------
// Row L2-norm inverse
// ---------------------------------------------------------------------------
__global__ void norm_k(const float* __restrict__ qkv, float* __restrict__ inv) {
    const int row = blockIdx.x;
    const int b = row >> 10, o = row & 1023;
    const float* p = qkv + ((size_t)b * 1536 + o) * N_TOK;
    float ss = 0.f;
    for (int i = threadIdx.x; i < N_TOK; i += 256) {
        float v = p[i];
        ss += v * v;
    }
#pragma unroll
    for (int off = 16; off; off >>= 1)
        ss += __shfl_xor_sync(0xffffffffu, ss, off);
    __shared__ float red[8];
    if ((threadIdx.x & 31) == 0) red[threadIdx.x >> 5] = ss;
    __syncthreads();
    if (threadIdx.x == 0) {
        float t = 0.f;
#pragma unroll
        for (int i = 0; i < 8; i++) t += red[i];
        inv[row] = 1.f / fmaxf(sqrtf(t), 1e-12f);
    }
}

// ---------------------------------------------------------------------------
// Flash attention v4: 256 queries/block, 16 warps x 16 rows, 512 threads,
// register-resident Q fragments, register-P, cp.async double-buffered K/V.
// Smem (floats): Qt[64][264] | Ks[2][64][72] | Vs[2][64][68]
// ---------------------------------------------------------------------------
#define QT_STR 264
#define KS_STR 72
#define VS_STR 68
#define KS_OFF (64 * QT_STR)
#define VS_OFF (KS_OFF + 2 * 64 * KS_STR)
#define ATTN_SMEM ((VS_OFF + 2 * 64 * VS_STR) * 4)  // 139264 B

__global__ __launch_bounds__(512, 1) void attn4(
    const float* __restrict__ qkv, const float* __restrict__ inv,
    float* __restrict__ out) {
    extern __shared__ float sm[];
    float* Qt = sm;
    float* KsBase = sm + KS_OFF;
    float* VsBase = sm + VS_OFF;

    const int tid = threadIdx.x, lane = tid & 31, w = tid >> 5;   // w: 0..15
    const int g = lane >> 2, tg = lane & 3;
    const int jj = (g >> 1) | ((g & 1) << 2);   // S-phase column permutation
    const int n0 = blockIdx.x * 256;
    const int h = blockIdx.y, b = blockIdx.z;
    const int i0 = w * 16;

    const float* qb = qkv + ((size_t)b * 1536 + h * 64) * N_TOK;
    const float* kb = qb + (size_t)512 * N_TOK;
    const float* vb = qb + (size_t)1024 * N_TOK;
    const float* invq = inv + b * 1024 + h * 64;
    const float* invk = invq + 512;

    const unsigned sBase = (unsigned)__cvta_generic_to_shared(sm);

    auto issueKV = [&](int t0, int buf) {
#pragma unroll
        for (int e = tid; e < 1024; e += 512) {
            int d = e >> 4, mq = e & 15;
            cp16(sBase + (KS_OFF + buf * 64 * KS_STR + d * KS_STR + mq * 4) * 4,
                 kb + (size_t)d * N_TOK + t0 + mq * 4);
            cp16(sBase + (VS_OFF + buf * 64 * VS_STR + d * VS_STR + mq * 4) * 4,
                 vb + (size_t)d * N_TOK + t0 + mq * 4);
        }
        CP_COMMIT;
    };

    issueKV(0, 0);

    // Stage Q d-major, scaled by invq*invk, rna-rounded
    for (int e = tid; e < 4096; e += 512) {
        int d = e >> 6, i4 = e & 63;
        float4 t = *(const float4*)(qb + (size_t)d * N_TOK + n0 + i4 * 4);
        float s = invq[d] * invk[d];
        float4 r = make_float4(to_tf32(t.x * s), to_tf32(t.y * s),
                               to_tf32(t.z * s), to_tf32(t.w * s));
        *(float4*)(&Qt[d * QT_STR + i4 * 4]) = r;
    }
    __syncthreads();

    // Hoist Q fragments to registers (reused for all 36 KV tiles)
    unsigned qa[8][4];
#pragma unroll
    for (int kbk = 0; kbk < 8; kbk++) {
        qa[kbk][0] = fb(Qt[(kbk * 8 + tg) * QT_STR + i0 + g]);
        qa[kbk][1] = fb(Qt[(kbk * 8 + tg) * QT_STR + i0 + g + 8]);
        qa[kbk][2] = fb(Qt[(kbk * 8 + tg + 4) * QT_STR + i0 + g]);
        qa[kbk][3] = fb(Qt[(kbk * 8 + tg + 4) * QT_STR + i0 + g + 8]);
    }

    float O[8][4] = {};
    float mx0 = -1e30f, mx1 = -1e30f, ls0 = 0.f, ls1 = 0.f;

    for (int t0 = 0; t0 < N_TOK; t0 += 64) {
        int buf = (t0 >> 6) & 1;
        if (t0 + 64 < N_TOK) { issueKV(t0 + 64, buf ^ 1); CP_WAIT(1); }
        else                 { CP_WAIT(0); }
        __syncthreads();
        const float* Kb = KsBase + buf * 64 * KS_STR;
        const float* Vb = VsBase + buf * 64 * VS_STR;

        // S-phase: S(16x64) = Q_rows x K (columns permuted by jj)
        float S[8][4] = {};
#pragma unroll
        for (int kbk = 0; kbk < 8; kbk++) {
            int k0 = kbk * 8;
#pragma unroll
            for (int nf = 0; nf < 8; nf++) {
                unsigned bb[2];
                bb[0] = fb(Kb[(k0 + tg) * KS_STR + nf * 8 + jj]);
                bb[1] = fb(Kb[(k0 + tg + 4) * KS_STR + nf * 8 + jj]);
                mma_tf32(S[nf], qa[kbk], bb);
            }
        }

        // Online softmax: rows g [c0,c1] and g+8 [c2,c3]
        float r0 = -1e30f, r1 = -1e30f;
#pragma unroll
        for (int nf = 0; nf < 8; nf++) {
            r0 = fmaxf(r0, fmaxf(S[nf][0], S[nf][1]));
            r1 = fmaxf(r1, fmaxf(S[nf][2], S[nf][3]));
        }
        r0 = fmaxf(r0, __shfl_xor_sync(0xffffffffu, r0, 1));
        r0 = fmaxf(r0, __shfl_xor_sync(0xffffffffu, r0, 2));
        r1 = fmaxf(r1, __shfl_xor_sync(0xffffffffu, r1, 1));
        r1 = fmaxf(r1, __shfl_xor_sync(0xffffffffu, r1, 2));
        float mn0 = fmaxf(mx0, r0), mn1 = fmaxf(mx1, r1);
        float c0 = __expf(mx0 - mn0), c1 = __expf(mx1 - mn1);
        mx0 = mn0; mx1 = mn1;
        float s0 = 0.f, s1 = 0.f;
#pragma unroll
        for (int nf = 0; nf < 8; nf++) {
            S[nf][0] = __expf(S[nf][0] - mn0);
            S[nf][1] = __expf(S[nf][1] - mn0);
            S[nf][2] = __expf(S[nf][2] - mn1);
            S[nf][3] = __expf(S[nf][3] - mn1);
            s0 += S[nf][0] + S[nf][1];
            s1 += S[nf][2] + S[nf][3];
        }
        s0 += __shfl_xor_sync(0xffffffffu, s0, 1);
        s0 += __shfl_xor_sync(0xffffffffu, s0, 2);
        s1 += __shfl_xor_sync(0xffffffffu, s1, 1);
        s1 += __shfl_xor_sync(0xffffffffu, s1, 2);
        ls0 = ls0 * c0 + s0;
        ls1 = ls1 * c1 + s1;
#pragma unroll
        for (int nf = 0; nf < 8; nf++) {
            O[nf][0] *= c0; O[nf][1] *= c0;
            O[nf][2] *= c1; O[nf][3] *= c1;
        }

        // PV-phase: A = P (registers via permutation identity), B = V^T
#pragma unroll
        for (int kk = 0; kk < 8; kk++) {
            unsigned pa[4];
            pa[0] = fb(S[kk][0]);
            pa[1] = fb(S[kk][2]);
            pa[2] = fb(S[kk][1]);
            pa[3] = fb(S[kk][3]);
#pragma unroll
            for (int nf = 0; nf < 8; nf++) {
                unsigned bb[2];
                bb[0] = fb(Vb[(nf * 8 + g) * VS_STR + kk * 8 + tg]);
                bb[1] = fb(Vb[(nf * 8 + g) * VS_STR + kk * 8 + tg + 4]);
                mma_tf32(O[nf], pa, bb);
            }
        }
        __syncthreads();   // protect Ks/Vs before next staging
    }

    // Epilogue: normalize, stage d-major via smem (reuse Ks region), store
    float* Os = KsBase;   // 64 x 136
    float* ob = out + ((size_t)b * 512 + h * 64) * N_TOK;
    float rl0 = 1.f / ls0, rl1 = 1.f / ls1;
#pragma unroll
    for (int pass = 0; pass < 2; pass++) {
        __syncthreads();
        if ((w >> 3) == pass) {
            int base = (w & 7) * 16;
            int ir0 = base + g, ir1 = base + g + 8;
#pragma unroll
            for (int nf = 0; nf < 8; nf++) {
                int d0 = nf * 8 + 2 * tg;
                Os[d0 * 136 + ir0]       = O[nf][0] * rl0;
                Os[(d0 + 1) * 136 + ir0] = O[nf][1] * rl0;
                Os[d0 * 136 + ir1]       = O[nf][2] * rl1;
                Os[(d0 + 1) * 136 + ir1] = O[nf][3] * rl1;
            }
        }
        __syncthreads();
        for (int e = tid; e < 2048; e += 512) {
            int d = e >> 5, i4 = e & 31;
            float4 t = *(const float4*)(&Os[d * 136 + i4 * 4]);
            *(float4*)(ob + (size_t)d * N_TOK + n0 + pass * 128 + i4 * 4) = t;
        }
    }
}

// ---------------------------------------------------------------------------
extern "C" void kernel_launch(void* const* d_in, const int* in_sizes, int n_in,
                              void* d_out, int out_size) {
    (void)in_sizes; (void)n_in; (void)out_size;
    const float* x      = (const float*)d_in[0];
    const float* w_qkv  = (const float*)d_in[1];
    const float* w_proj = (const float*)d_in[2];
    const float* b_proj = (const float*)d_in[3];
    float* y = (float*)d_out;

    float *qkv_p, *inv_p, *att_p, *w1_p, *w2_p;
    cudaGetSymbolAddress((void**)&qkv_p, g_qkv);
    cudaGetSymbolAddress((void**)&inv_p, g_inv);
    cudaGetSymbolAddress((void**)&att_p, g_att);
    cudaGetSymbolAddress((void**)&w1_p, g_w1);
    cudaGetSymbolAddress((void**)&w2_p, g_w2);

    cudaFuncSetAttribute(attn4, cudaFuncAttributeMaxDynamicSharedMemorySize,
                         ATTN_SMEM);

    // 0) pre-round weights to tf32
    round_w<<<1536, 256>>>(w_qkv, w_proj, w1_p, w2_p, 1536 * 256, 256 * 512);
    // 1) qkv = w_qkv @ x   (M=1536, K=256)
    gemm2<128, 32><<<dim3(18, 12, 2), 256>>>(w1_p, x, nullptr, qkv_p, 256, 1536);
    // 2) inverse L2 norms
    norm_k<<<2048, 256>>>(qkv_p, inv_p);
    // 3) flash attention (512 threads, 16 warps)
    attn4<<<dim3(9, 8, 2), 512, ATTN_SMEM>>>(qkv_p, inv_p, att_p);
    // 4) y = w_proj @ att + b_proj   (M=256, K=512)
    gemm2<64, 16><<<dim3(18, 4, 2), 256>>>(w2_p, att_p, b_proj, y, 512, 256);
}

// round 6
// speedup vs baseline: 1.2530x; 1.2530x over previous
#include <cuda_runtime.h>
#include <math.h>

#define N_TOK 2304
#define LOG2E 1.4426950408889634f

// Scratch (device globals: allocation-free per harness rules)
__device__ float g_qkv[2u * 1536u * 2304u];   // (B, 3*512, N)
__device__ float g_inv[2 * 1024];             // inv L2 norms: q rows 0..511, k rows 512..1023
__device__ float g_att[2u * 512u * 2304u];    // attention output (B, 512, N)
__device__ float g_w1[1536 * 256];            // tf32-rounded w_qkv
__device__ float g_w2[256 * 512];             // tf32-rounded w_proj

__device__ __forceinline__ float to_tf32(float x) {
    float r;
    asm("cvt.rna.tf32.f32 %0, %1;" : "=f"(r) : "f"(x));
    return r;
}
__device__ __forceinline__ float ex2(float x) {
    float r;
    asm("ex2.approx.f32 %0, %1;" : "=f"(r) : "f"(x));
    return r;
}
__device__ __forceinline__ unsigned fb(float x) { return __float_as_uint(x); }

__device__ __forceinline__ void mma_tf32(float* d, const unsigned* a, const unsigned* b) {
    asm volatile(
        "mma.sync.aligned.m16n8k8.row.col.f32.tf32.tf32.f32 "
        "{%0,%1,%2,%3}, {%4,%5,%6,%7}, {%8,%9}, {%0,%1,%2,%3};\n"
        : "+f"(d[0]), "+f"(d[1]), "+f"(d[2]), "+f"(d[3])
        : "r"(a[0]), "r"(a[1]), "r"(a[2]), "r"(a[3]), "r"(b[0]), "r"(b[1]));
}

__device__ __forceinline__ void cp16(unsigned dst, const void* src) {
    asm volatile("cp.async.ca.shared.global [%0], [%1], 16;" :: "r"(dst), "l"(src));
}
#define CP_COMMIT asm volatile("cp.async.commit_group;")
#define CP_WAIT(n) asm volatile("cp.async.wait_group %0;" :: "n"(n))

// ---------------------------------------------------------------------------
// Pre-round weights to tf32 (once, cheap)
// ---------------------------------------------------------------------------
__global__ void round_w(const float* __restrict__ a, const float* __restrict__ b,
                        float* __restrict__ wa, float* __restrict__ wb,
                        int na, int nb) {
    int i = blockIdx.x * 256 + threadIdx.x;
    if (i < na) wa[i] = to_tf32(a[i]);
    if (i < nb) wb[i] = to_tf32(b[i]);
}

// ---------------------------------------------------------------------------
// tf32 GEMM: Y[b][m][n] = sum_k W[m][k]*X[b][k][n] (+bias[m])
// Block tile BM x 128, 8 warps (4m x 2n), warp WM x 64, k-chunk 16, cp.async x2.
// ---------------------------------------------------------------------------
template <int BM, int WM>
__global__ __launch_bounds__(256) void gemm2(
    const float* __restrict__ W, const float* __restrict__ X,
    const float* __restrict__ bias, float* __restrict__ Y, int K, int Mtot) {
    constexpr int NG = WM / 16;
    __shared__ float As[2][BM * 20];     // [m][k] stride 20
    __shared__ float Bs[2][16 * 136];    // [k][n] stride 136

    const int tid = threadIdx.x, lane = tid & 31, w = tid >> 5;
    const int g = lane >> 2, tg = lane & 3;
    const int wm0 = (w & 3) * WM, wn0 = (w >> 2) * 64;
    const int n0 = blockIdx.x * 128;
    const int m0 = blockIdx.y * BM;
    const int b  = blockIdx.z;
    const float* Xb = X + (size_t)b * K * N_TOK;
    float* Yb = Y + (size_t)b * Mtot * N_TOK;

    const unsigned sA = (unsigned)__cvta_generic_to_shared(&As[0][0]);
    const unsigned sB = (unsigned)__cvta_generic_to_shared(&Bs[0][0]);

    float acc[NG][8][4] = {};

    auto issue = [&](int k0, int buf) {
#pragma unroll
        for (int e = tid; e < BM * 4; e += 256) {
            int m = e >> 2, kq = e & 3;
            cp16(sA + (buf * BM * 20 + m * 20 + kq * 4) * 4,
                 W + (size_t)(m0 + m) * K + k0 + kq * 4);
        }
#pragma unroll
        for (int e = tid; e < 512; e += 256) {
            int kk = e >> 5, nq = e & 31;
            cp16(sB + (buf * 16 * 136 + kk * 136 + nq * 4) * 4,
                 Xb + (size_t)(k0 + kk) * N_TOK + n0 + nq * 4);
        }
        CP_COMMIT;
    };

    issue(0, 0);
    for (int k0 = 0; k0 < K; k0 += 16) {
        int buf = (k0 >> 4) & 1;
        if (k0 + 16 < K) { issue(k0 + 16, buf ^ 1); CP_WAIT(1); }
        else             { CP_WAIT(0); }
        __syncthreads();
        const float* Ab = As[buf];
        const float* Bb = Bs[buf];
#pragma unroll
        for (int kc = 0; kc < 16; kc += 8) {
            unsigned a[NG][4];
#pragma unroll
            for (int s = 0; s < NG; s++) {
                int r = wm0 + 16 * s + g;
                a[s][0] = fb(Ab[r * 20 + kc + tg]);
                a[s][1] = fb(Ab[(r + 8) * 20 + kc + tg]);
                a[s][2] = fb(Ab[r * 20 + kc + tg + 4]);
                a[s][3] = fb(Ab[(r + 8) * 20 + kc + tg + 4]);
            }
#pragma unroll
            for (int nf = 0; nf < 8; nf++) {
                unsigned bb[2];
                bb[0] = fb(Bb[(kc + tg) * 136 + wn0 + nf * 8 + g]);
                bb[1] = fb(Bb[(kc + tg + 4) * 136 + wn0 + nf * 8 + g]);
#pragma unroll
                for (int s = 0; s < NG; s++) mma_tf32(acc[s][nf], a[s], bb);
            }
        }
        __syncthreads();
    }
#pragma unroll
    for (int s = 0; s < NG; s++) {
        int r0 = m0 + wm0 + 16 * s + g, r1 = r0 + 8;
        float bv0 = bias ? bias[r0] : 0.f;
        float bv1 = bias ? bias[r1] : 0.f;
#pragma unroll
        for (int nf = 0; nf < 8; nf++) {
            *(float2*)(Yb + (size_t)r0 * N_TOK + n0 + wn0 + nf * 8 + tg * 2) =
                make_float2(acc[s][nf][0] + bv0, acc[s][nf][1] + bv0);
            *(float2*)(Yb + (size_t)r1 * N_TOK + n0 + wn0 + nf * 8 + tg * 2) =
                make_float2(acc[s][nf][2] + bv1, acc[s][nf][3] + bv1);
        }
    }
}

// ---------------------------------------------------------------------------
// Row L2-norm inverse
// ---------------------------------------------------------------------------
__global__ void norm_k(const float* __restrict__ qkv, float* __restrict__ inv) {
    const int row = blockIdx.x;
    const int b = row >> 10, o = row & 1023;
    const float* p = qkv + ((size_t)b * 1536 + o) * N_TOK;
    float ss = 0.f;
    for (int i = threadIdx.x; i < N_TOK; i += 256) {
        float v = p[i];
        ss += v * v;
    }
#pragma unroll
    for (int off = 16; off; off >>= 1)
        ss += __shfl_xor_sync(0xffffffffu, ss, off);
    __shared__ float red[8];
    if ((threadIdx.x & 31) == 0) red[threadIdx.x >> 5] = ss;
    __syncthreads();
    if (threadIdx.x == 0) {
        float t = 0.f;
#pragma unroll
        for (int i = 0; i < 8; i++) t += red[i];
        inv[row] = 1.f / fmaxf(sqrtf(t), 1e-12f);
    }
}

// ---------------------------------------------------------------------------
// Flash attention v5: 256 queries/block, 8 warps x 32 rows, 256 threads.
// - S = cos-sim in [-1,1] (L2-normed q,k) -> NO online max, NO O rescale,
//   deferred l-reduction; exp via single ex2 (log2e folded into Q scale).
// - Q stored lane-private fragment-packed (float4) in smem.
// - cp.async double-buffered K/V.
// Smem (floats): Qf[16384] | Ks[2][64][72] | Vs[2][64][68]
// ---------------------------------------------------------------------------
#define KS_STR 72
#define VS_STR 68
#define KS_OFF 16384
#define VS_OFF (KS_OFF + 2 * 64 * KS_STR)            // 25600
#define ATTN_SMEM ((VS_OFF + 2 * 64 * VS_STR) * 4)   // 137216 B

__global__ __launch_bounds__(256, 1) void attn5(
    const float* __restrict__ qkv, const float* __restrict__ inv,
    float* __restrict__ out) {
    extern __shared__ float sm[];
    float4* Qf = (float4*)sm;          // [(w*2+grp)*8+kbk][lane]
    float* KsBase = sm + KS_OFF;
    float* VsBase = sm + VS_OFF;

    const int tid = threadIdx.x, lane = tid & 31, w = tid >> 5;
    const int g = lane >> 2, tg = lane & 3;
    const int jj = (g >> 1) | ((g & 1) << 2);   // S-phase column permutation
    const int n0 = blockIdx.x * 256;
    const int h = blockIdx.y, b = blockIdx.z;
    const int i0 = w * 32;

    const float* qb = qkv + ((size_t)b * 1536 + h * 64) * N_TOK;
    const float* kb = qb + (size_t)512 * N_TOK;
    const float* vb = qb + (size_t)1024 * N_TOK;
    const float* invq = inv + b * 1024 + h * 64;
    const float* invk = invq + 512;

    const unsigned sBase = (unsigned)__cvta_generic_to_shared(sm);

    auto issueKV = [&](int t0, int buf) {
#pragma unroll
        for (int e = tid; e < 1024; e += 256) {
            int d = e >> 4, mq = e & 15;
            cp16(sBase + (KS_OFF + buf * 64 * KS_STR + d * KS_STR + mq * 4) * 4,
                 kb + (size_t)d * N_TOK + t0 + mq * 4);
            cp16(sBase + (VS_OFF + buf * 64 * VS_STR + d * VS_STR + mq * 4) * 4,
                 vb + (size_t)d * N_TOK + t0 + mq * 4);
        }
        CP_COMMIT;
    };

    issueKV(0, 0);

    // Stage Q lane-private fragment-packed, scaled by invq*invk*log2e
#pragma unroll
    for (int grp = 0; grp < 2; grp++) {
#pragma unroll
        for (int kbk = 0; kbk < 8; kbk++) {
            int d0 = kbk * 8 + tg, d1 = d0 + 4;
            int r = n0 + i0 + grp * 16 + g;
            float s0 = invq[d0] * invk[d0] * LOG2E;
            float s1 = invq[d1] * invk[d1] * LOG2E;
            float4 v;
            v.x = to_tf32(qb[(size_t)d0 * N_TOK + r] * s0);
            v.y = to_tf32(qb[(size_t)d0 * N_TOK + r + 8] * s0);
            v.z = to_tf32(qb[(size_t)d1 * N_TOK + r] * s1);
            v.w = to_tf32(qb[(size_t)d1 * N_TOK + r + 8] * s1);
            Qf[((w * 2 + grp) * 8 + kbk) * 32 + lane] = v;
        }
    }

    float O[2][8][4] = {};
    float l00 = 0.f, l01 = 0.f, l10 = 0.f, l11 = 0.f;  // [grp][rowhalf]

    for (int t0 = 0; t0 < N_TOK; t0 += 64) {
        int buf = (t0 >> 6) & 1;
        if (t0 + 64 < N_TOK) { issueKV(t0 + 64, buf ^ 1); CP_WAIT(1); }
        else                 { CP_WAIT(0); }
        __syncthreads();
        const float* Kb = KsBase + buf * 64 * KS_STR;
        const float* Vb = VsBase + buf * 64 * VS_STR;

        // S-phase (columns permuted by jj); A-frags as single LDS.128
        float S[2][8][4] = {};
#pragma unroll
        for (int kbk = 0; kbk < 8; kbk++) {
            int k0 = kbk * 8;
            float4 a0f = Qf[((w * 2 + 0) * 8 + kbk) * 32 + lane];
            float4 a1f = Qf[((w * 2 + 1) * 8 + kbk) * 32 + lane];
            unsigned a0[4] = {fb(a0f.x), fb(a0f.y), fb(a0f.z), fb(a0f.w)};
            unsigned a1[4] = {fb(a1f.x), fb(a1f.y), fb(a1f.z), fb(a1f.w)};
#pragma unroll
            for (int nf = 0; nf < 8; nf++) {
                unsigned bb[2];
                bb[0] = fb(Kb[(k0 + tg) * KS_STR + nf * 8 + jj]);
                bb[1] = fb(Kb[(k0 + tg + 4) * KS_STR + nf * 8 + jj]);
                mma_tf32(S[0][nf], a0, bb);
                mma_tf32(S[1][nf], a1, bb);
            }
        }

        // Bounded softmax: P = exp2(S) directly (S already scaled by log2e),
        // per-lane l accumulation, no max, no rescale.
#pragma unroll
        for (int nf = 0; nf < 8; nf++) {
            S[0][nf][0] = ex2(S[0][nf][0]); S[0][nf][1] = ex2(S[0][nf][1]);
            S[0][nf][2] = ex2(S[0][nf][2]); S[0][nf][3] = ex2(S[0][nf][3]);
            S[1][nf][0] = ex2(S[1][nf][0]); S[1][nf][1] = ex2(S[1][nf][1]);
            S[1][nf][2] = ex2(S[1][nf][2]); S[1][nf][3] = ex2(S[1][nf][3]);
            l00 += S[0][nf][0] + S[0][nf][1];
            l01 += S[0][nf][2] + S[0][nf][3];
            l10 += S[1][nf][0] + S[1][nf][1];
            l11 += S[1][nf][2] + S[1][nf][3];
        }

        // PV-phase: A = P (registers via permutation identity), B = V^T
#pragma unroll
        for (int kk = 0; kk < 8; kk++) {
            unsigned pa0[4], pa1[4];
            pa0[0] = fb(S[0][kk][0]); pa0[1] = fb(S[0][kk][2]);
            pa0[2] = fb(S[0][kk][1]); pa0[3] = fb(S[0][kk][3]);
            pa1[0] = fb(S[1][kk][0]); pa1[1] = fb(S[1][kk][2]);
            pa1[2] = fb(S[1][kk][1]); pa1[3] = fb(S[1][kk][3]);
#pragma unroll
            for (int nf = 0; nf < 8; nf++) {
                unsigned bb[2];
                bb[0] = fb(Vb[(nf * 8 + g) * VS_STR + kk * 8 + tg]);
                bb[1] = fb(Vb[(nf * 8 + g) * VS_STR + kk * 8 + tg + 4]);
                mma_tf32(O[0][nf], pa0, bb);
                mma_tf32(O[1][nf], pa1, bb);
            }
        }
        __syncthreads();   // protect Ks/Vs before next staging
    }

    // Deferred l-reduction over the 4 lanes (tg) sharing each row
    l00 += __shfl_xor_sync(0xffffffffu, l00, 1);
    l00 += __shfl_xor_sync(0xffffffffu, l00, 2);
    l01 += __shfl_xor_sync(0xffffffffu, l01, 1);
    l01 += __shfl_xor_sync(0xffffffffu, l01, 2);
    l10 += __shfl_xor_sync(0xffffffffu, l10, 1);
    l10 += __shfl_xor_sync(0xffffffffu, l10, 2);
    l11 += __shfl_xor_sync(0xffffffffu, l11, 1);
    l11 += __shfl_xor_sync(0xffffffffu, l11, 2);
    float rl[2][2] = {{1.f / l00, 1.f / l01}, {1.f / l10, 1.f / l11}};

    // Epilogue: stage d-major via smem (reuse Ks region), store
    float* Os = KsBase;   // 64 x 136
    float* ob = out + ((size_t)b * 512 + h * 64) * N_TOK;
#pragma unroll
    for (int pass = 0; pass < 2; pass++) {
        __syncthreads();
        if ((w >> 2) == pass) {
            int base = (w & 3) * 32;
#pragma unroll
            for (int grp = 0; grp < 2; grp++) {
                int ir0 = base + 16 * grp + g, ir1 = ir0 + 8;
#pragma unroll
                for (int nf = 0; nf < 8; nf++) {
                    int d0 = nf * 8 + 2 * tg;
                    Os[d0 * 136 + ir0]       = O[grp][nf][0] * rl[grp][0];
                    Os[(d0 + 1) * 136 + ir0] = O[grp][nf][1] * rl[grp][0];
                    Os[d0 * 136 + ir1]       = O[grp][nf][2] * rl[grp][1];
                    Os[(d0 + 1) * 136 + ir1] = O[grp][nf][3] * rl[grp][1];
                }
            }
        }
        __syncthreads();
        for (int e = tid; e < 2048; e += 256) {
            int d = e >> 5, i4 = e & 31;
            float4 t = *(const float4*)(&Os[d * 136 + i4 * 4]);
            *(float4*)(ob + (size_t)d * N_TOK + n0 + pass * 128 + i4 * 4) = t;
        }
    }
}

// ---------------------------------------------------------------------------
extern "C" void kernel_launch(void* const* d_in, const int* in_sizes, int n_in,
                              void* d_out, int out_size) {
    (void)in_sizes; (void)n_in; (void)out_size;
    const float* x      = (const float*)d_in[0];
    const float* w_qkv  = (const float*)d_in[1];
    const float* w_proj = (const float*)d_in[2];
    const float* b_proj = (const float*)d_in[3];
    float* y = (float*)d_out;

    float *qkv_p, *inv_p, *att_p, *w1_p, *w2_p;
    cudaGetSymbolAddress((void**)&qkv_p, g_qkv);
    cudaGetSymbolAddress((void**)&inv_p, g_inv);
    cudaGetSymbolAddress((void**)&att_p, g_att);
    cudaGetSymbolAddress((void**)&w1_p, g_w1);
    cudaGetSymbolAddress((void**)&w2_p, g_w2);

    cudaFuncSetAttribute(attn5, cudaFuncAttributeMaxDynamicSharedMemorySize,
                         ATTN_SMEM);

    // 0) pre-round weights to tf32
    round_w<<<1536, 256>>>(w_qkv, w_proj, w1_p, w2_p, 1536 * 256, 256 * 512);
    // 1) qkv = w_qkv @ x   (M=1536, K=256)
    gemm2<128, 32><<<dim3(18, 12, 2), 256>>>(w1_p, x, nullptr, qkv_p, 256, 1536);
    // 2) inverse L2 norms
    norm_k<<<2048, 256>>>(qkv_p, inv_p);
    // 3) flash attention v5
    attn5<<<dim3(9, 8, 2), 256, ATTN_SMEM>>>(qkv_p, inv_p, att_p);
    // 4) y = w_proj @ att + b_proj   (M=256, K=512)
    gemm2<64, 16><<<dim3(18, 4, 2), 256>>>(w2_p, att_p, b_proj, y, 512, 256);
}